// round 14
// baseline (speedup 1.0000x reference)
#include <cuda_runtime.h>
#include <cstdint>

// ALIF forward scan — 4-phase load pipeline + smem-staged 64-line store bursts.
// x_seq: [T, n_flat] fp32; state v, a: [n_flat]; out spikes [T, n_flat] fp32.
// Per step: v = dv*v + x; th = th0 + beta*a; s = (v>th); v -= s*th; a = da*a + s.
//
// Thread-per-neuron, sequential T. Loads: 4-phase rotation of 8-element
// batches, consumed 3 batches (24 steps) after issue. Stores: spikes for 8
// batches (64 steps) are staged in shared memory (STS issue-only, conflict-free
// lane mapping, no cross-thread sharing -> no syncs), then drained as a 64-line
// same-direction STG burst. Coarser write bursts reduce DRAM read/write
// turnaround (confirmed direction in R13: 32-line bursts gained ~3% BW).

#define U 8        // timesteps per batch
#define PER 8      // batches per store period (64 steps)
#define BLKN 64    // threads per CTA

__device__ __forceinline__ float alif_step(float& v, float& a, float xv,
                                           float dv, float da, float th0, float beta) {
    v = fmaf(dv, v, xv);
    float th = fmaf(beta, a, th0);
    float s = (v > th) ? 1.0f : 0.0f;
    v = fmaf(-s, th, v);
    a = fmaf(da, a, s);
    return s;
}

__global__ __launch_bounds__(BLKN)
void ALIF_24309514895931_kernel(const float* __restrict__ x,
                                const float* __restrict__ v0,
                                const float* __restrict__ a0,
                                const float* __restrict__ dv_p,
                                const float* __restrict__ da_p,
                                const float* __restrict__ th_p,
                                const float* __restrict__ beta_p,
                                float* __restrict__ out,
                                int n_flat, int T) {
    __shared__ float stage[PER * U * BLKN];   // 16 KB: 64 steps x 64 threads

    int tid = threadIdx.x;
    int i = blockIdx.x * BLKN + tid;
    if (i >= n_flat) return;

    const float dv   = *dv_p;
    const float da   = *da_p;
    const float th0  = *th_p;
    const float beta = *beta_p;

    float v = v0[i];
    float a = a0[i];

    const float* xp = x + i;
    float* op = out + i;
    const unsigned int stride = (unsigned int)n_flat;

    float* lane = stage + tid;   // this thread's column; bank-conflict-free

    const int nb = T / U;

    float b0[U], b1[U], b2[U], b3[U];

#define LOADBLK(buf, bi)                                                    \
    {                                                                       \
        unsigned int base = (unsigned int)(bi) * U * stride;                \
        _Pragma("unroll")                                                   \
        for (int k = 0; k < U; k++)                                         \
            (buf)[k] = __ldcs(xp + base + (unsigned int)k * stride);        \
    }

    // Compute one batch; stage spikes into smem at period slot p (0..PER-1).
#define COMPSTAGE(buf, p)                                                   \
    {                                                                       \
        _Pragma("unroll")                                                   \
        for (int k = 0; k < U; k++)                                         \
            lane[((p) * U + k) * BLKN] =                                    \
                alif_step(v, a, (buf)[k], dv, da, th0, beta);               \
    }

    int g = 0;
    if (nb >= PER) {
        // Prologue: batches 0,1,2 in flight.
        LOADBLK(b0, 0);
        LOADBLK(b1, 1);
        LOADBLK(b2, 2);

        for (; g + PER <= nb; g += PER) {
            // 8 phases: load batch g+p+3 into buf[(p+3)%4], compute batch g+p
            // from buf[p%4] into the smem stage.
            if (g + 3 < nb) LOADBLK(b3, g + 3);
            COMPSTAGE(b0, 0);
            if (g + 4 < nb) LOADBLK(b0, g + 4);
            COMPSTAGE(b1, 1);
            if (g + 5 < nb) LOADBLK(b1, g + 5);
            COMPSTAGE(b2, 2);
            if (g + 6 < nb) LOADBLK(b2, g + 6);
            COMPSTAGE(b3, 3);
            if (g + 7 < nb) LOADBLK(b3, g + 7);
            COMPSTAGE(b0, 4);
            if (g + 8 < nb) LOADBLK(b0, g + 8);
            COMPSTAGE(b1, 5);
            if (g + 9 < nb) LOADBLK(b1, g + 9);
            COMPSTAGE(b2, 6);
            if (g + 10 < nb) LOADBLK(b2, g + 10);
            COMPSTAGE(b3, 7);

            // Drain: 64-line same-direction store burst.
            unsigned int base = (unsigned int)g * U * stride;
            #pragma unroll
            for (int j = 0; j < PER * U; j++)
                __stcs(op + base + (unsigned int)j * stride, lane[j * BLKN]);
        }
    }

    // Remainder (batches g..nb-1 and T%U tail): simple scalar path.
    for (int t = g * U; t < T; t++) {
        float xv = __ldcs(xp + (unsigned int)t * stride);
        float s = alif_step(v, a, xv, dv, da, th0, beta);
        __stcs(op + (unsigned int)t * stride, s);
    }
#undef LOADBLK
#undef COMPSTAGE
}

extern "C" void kernel_launch(void* const* d_in, const int* in_sizes, int n_in,
                              void* d_out, int out_size) {
    // metadata order: x_seq, v, a, decay_v, decay_a, threshold, beta, alpha
    const float* x      = (const float*)d_in[0];
    const float* v0     = (const float*)d_in[1];
    const float* a0     = (const float*)d_in[2];
    const float* dv_p   = (const float*)d_in[3];
    const float* da_p   = (const float*)d_in[4];
    const float* th_p   = (const float*)d_in[5];
    const float* beta_p = (const float*)d_in[6];
    // alpha (d_in[7]) only affects backward surrogate; unused in forward.

    int n_flat = in_sizes[1];
    int T      = in_sizes[0] / n_flat;

    float* out = (float*)d_out;

    int blocks = (n_flat + BLKN - 1) / BLKN;   // 1024 for n_flat=65536
    ALIF_24309514895931_kernel<<<blocks, BLKN>>>(
        x, v0, a0, dv_p, da_p, th_p, beta_p, out, n_flat, T);
}